// round 12
// baseline (speedup 1.0000x reference)
#include <cuda_runtime.h>

// Patch2Im gather: residue-major lanes + specialized bodies + 4-way channel
// batching with EXPLICIT load/compute phase split (forces ptxas to issue all
// independent LDGs back-to-back => max memory-level parallelism).
// Channels consecutive (CSTEP=1) for DRAM locality.
// out[bc,h,w] = mean over valid (i,j) of xp[bc,i,j,ph,pw],
//   h+3 = i + 3*ph, w+3 = j + 3*pw.

#define PS 7225               // 85*85
#define CST (7 * PS)          // stride of i index
#define CHS (49 * PS)         // channel stride (per bc)
#define OH 253
#define OW 253
#define OCH (OH * OW)         // 64009
#define NCH 4

__global__ void __launch_bounds__(256)
patch2im_kernel(const float* __restrict__ xp, float* __restrict__ out)
{
    int s = threadIdx.x;
    if (s >= 253) return;
    int h   = blockIdx.x;             // 0..252
    int bc0 = blockIdx.y;             // 0..63 ; channels 4*bc0 .. 4*bc0+3

    // residue-major output mapping: [r=0: q=0..84][r=1: q=0..83][r=2: q=0..83]
    int r, q;
    if (s < 85)       { r = 0; q = s; }
    else if (s < 169) { r = 1; q = s - 85; }
    else              { r = 2; q = s - 169; }

    int hp = h + 3;                   // 3..255
    int qh = hp / 3;                  // 1..85
    int rh = hp % 3;

    const float* base = xp + (size_t)(4 * bc0) * CHS;
    float* op = out + (size_t)(4 * bc0) * OCH + (size_t)h * OW + (3 * q + r);

    if (rh == 0) {                    // rows i = 0,3,6 ; ph = qh, qh-1, qh-2
        float wr0 = (qh <= 84) ? 1.f : 0.f;
        float wr2 = (qh >= 2)  ? 1.f : 0.f;
        int ro0 = 0 * CST + ((qh <= 84) ? qh : 0) * 85;
        int ro1 = 3 * CST + (qh - 1) * 85;
        int ro2 = 6 * CST + ((qh >= 2) ? (qh - 2) : 0) * 85;
        float inr = (wr0 + wr2 == 2.f) ? (1.f / 3.f) : 0.5f;

        if (r == 0) {                 // 3x3 case: cols j = 0,3,6
            float wc0 = (q <= 83) ? 1.f : 0.f;
            float wc2 = (q >= 1)  ? 1.f : 0.f;
            int c0 = 0 * PS + ((q <= 83) ? q + 1 : 0);
            int c1 = 3 * PS + q;
            int c2 = 6 * PS + ((q >= 1) ? q - 1 : 0);
            float scale = inr * ((wc0 + wc2 == 2.f) ? (1.f / 3.f) : 0.5f);

            float v[NCH][9];
#pragma unroll
            for (int k = 0; k < NCH; ++k) {
                const float* b = base + (size_t)k * CHS;
                v[k][0] = __ldg(b + ro0 + c0); v[k][1] = __ldg(b + ro1 + c0); v[k][2] = __ldg(b + ro2 + c0);
                v[k][3] = __ldg(b + ro0 + c1); v[k][4] = __ldg(b + ro1 + c1); v[k][5] = __ldg(b + ro2 + c1);
                v[k][6] = __ldg(b + ro0 + c2); v[k][7] = __ldg(b + ro1 + c2); v[k][8] = __ldg(b + ro2 + c2);
            }
#pragma unroll
            for (int k = 0; k < NCH; ++k) {
                float s0 = wr0 * v[k][0] + v[k][1] + wr2 * v[k][2];
                float s1 = wr0 * v[k][3] + v[k][4] + wr2 * v[k][5];
                float s2 = wr0 * v[k][6] + v[k][7] + wr2 * v[k][8];
                op[(size_t)k * OCH] = (wc0 * s0 + s1 + wc2 * s2) * scale;
            }
        } else {                      // 3x2 case: cols j = r, r+3 (always valid)
            int c0 = r * PS + (q + 1);
            int c1 = (r + 3) * PS + q;
            float scale = inr * 0.5f;

            float v[NCH][6];
#pragma unroll
            for (int k = 0; k < NCH; ++k) {
                const float* b = base + (size_t)k * CHS;
                v[k][0] = __ldg(b + ro0 + c0); v[k][1] = __ldg(b + ro1 + c0); v[k][2] = __ldg(b + ro2 + c0);
                v[k][3] = __ldg(b + ro0 + c1); v[k][4] = __ldg(b + ro1 + c1); v[k][5] = __ldg(b + ro2 + c1);
            }
#pragma unroll
            for (int k = 0; k < NCH; ++k) {
                float s0 = wr0 * v[k][0] + v[k][1] + wr2 * v[k][2];
                float s1 = wr0 * v[k][3] + v[k][4] + wr2 * v[k][5];
                op[(size_t)k * OCH] = (s0 + s1) * scale;
            }
        }
    } else {                          // rows i = rh, rh+3 ; ph = qh, qh-1 (always valid)
        int ro0 = rh * CST + qh * 85;
        int ro1 = (rh + 3) * CST + (qh - 1) * 85;

        if (r == 0) {                 // 2x3 case
            float wc0 = (q <= 83) ? 1.f : 0.f;
            float wc2 = (q >= 1)  ? 1.f : 0.f;
            int c0 = 0 * PS + ((q <= 83) ? q + 1 : 0);
            int c1 = 3 * PS + q;
            int c2 = 6 * PS + ((q >= 1) ? q - 1 : 0);
            float scale = 0.5f * ((wc0 + wc2 == 2.f) ? (1.f / 3.f) : 0.5f);

            float v[NCH][6];
#pragma unroll
            for (int k = 0; k < NCH; ++k) {
                const float* b = base + (size_t)k * CHS;
                v[k][0] = __ldg(b + ro0 + c0); v[k][1] = __ldg(b + ro1 + c0);
                v[k][2] = __ldg(b + ro0 + c1); v[k][3] = __ldg(b + ro1 + c1);
                v[k][4] = __ldg(b + ro0 + c2); v[k][5] = __ldg(b + ro1 + c2);
            }
#pragma unroll
            for (int k = 0; k < NCH; ++k) {
                float s0 = v[k][0] + v[k][1];
                float s1 = v[k][2] + v[k][3];
                float s2 = v[k][4] + v[k][5];
                op[(size_t)k * OCH] = (wc0 * s0 + s1 + wc2 * s2) * scale;
            }
        } else {                      // 2x2 interior: count always 4 (66% of outputs)
            int c0 = r * PS + (q + 1);
            int c1 = (r + 3) * PS + q;

            float v[NCH][4];
#pragma unroll
            for (int k = 0; k < NCH; ++k) {
                const float* b = base + (size_t)k * CHS;
                v[k][0] = __ldg(b + ro0 + c0); v[k][1] = __ldg(b + ro1 + c0);
                v[k][2] = __ldg(b + ro0 + c1); v[k][3] = __ldg(b + ro1 + c1);
            }
#pragma unroll
            for (int k = 0; k < NCH; ++k)
                op[(size_t)k * OCH] = (v[k][0] + v[k][1] + v[k][2] + v[k][3]) * 0.25f;
        }
    }
}

extern "C" void kernel_launch(void* const* d_in, const int* in_sizes, int n_in,
                              void* d_out, int out_size)
{
    const float* xp = (const float*)d_in[0];
    float* outp = (float*)d_out;
    dim3 grid(OH, 64);                // (h, bc/4)
    patch2im_kernel<<<grid, 256>>>(xp, outp);
}